// round 2
// baseline (speedup 1.0000x reference)
#include <cuda_runtime.h>

// Problem constants
#define NJ   24
#define NP   32768
#define NF   42
#define NR   16
#define DIN  126     // = NF*3
#define HID  32
#define NIND 18
#define NOUTC 144
#define NFPAD 44     // feature f-dim padded for float4 loads

// Shared layout (floats)
#define OFF_W1   0                        // [126][32]                (4032)
#define OFF_HS   4032                     // 4 warps * 32o * 36 pad   (4608)
#define OFF_FEAT 8640                     // [c][x0][fpad] 3*16*44    (2112)
#define OFF_B1   10752                    // 32
#define OFF_B2   10784                    // 126
#define OFF_W2T  10910                    // [o][k] 32*126            (4032)
#define SMEM_FLOATS 14942                 // 59768 B

typedef unsigned long long ull;

__device__ __forceinline__ ull pack2(float lo, float hi) {
    ull r; asm("mov.b64 %0, {%1, %2};" : "=l"(r) : "f"(lo), "f"(hi)); return r;
}
__device__ __forceinline__ ull rep2(float v) { return pack2(v, v); }
__device__ __forceinline__ void unpack2(ull v, float& lo, float& hi) {
    asm("mov.b64 {%0, %1}, %2;" : "=f"(lo), "=f"(hi) : "l"(v));
}
__device__ __forceinline__ ull fma2(ull a, ull b, ull c) {
    ull d; asm("fma.rn.f32x2 %0, %1, %2, %3;" : "=l"(d) : "l"(a), "l"(b), "l"(c)); return d;
}

extern "C" __global__ void __launch_bounds__(128)
v3d_fused_kernel(const float* __restrict__ pts,
                 const float* __restrict__ feature,
                 const float* __restrict__ ind,
                 const float* __restrict__ w1,
                 const float* __restrict__ b1,
                 const float* __restrict__ w2,
                 const float* __restrict__ b2,
                 float* __restrict__ out)
{
    extern __shared__ float sm[];
    float* w1s   = sm + OFF_W1;
    float* hsall = sm + OFF_HS;
    float* sfeat = sm + OFF_FEAT;
    float* b1s   = sm + OFF_B1;
    float* b2s   = sm + OFF_B2;
    float* w2t   = sm + OFF_W2T;

    const int j    = blockIdx.y;
    const int tid  = threadIdx.x;
    const int lane = tid & 31;
    const int warp = tid >> 5;

    // ---- Stage per-volume constants ----
    {
        const float* w1g = w1 + j * (DIN * HID);
        for (int idx = tid; idx < DIN * HID; idx += 128) w1s[idx] = w1g[idx];
        const float* w2g = w2 + j * (HID * DIN);          // [o][k] row-major already
        for (int idx = tid; idx < HID * DIN; idx += 128) w2t[idx] = w2g[idx];
        const float* fg = feature + j * (NF * NR * 3);    // [f][r][c]
        for (int idx = tid; idx < NF * NR * 3; idx += 128) {
            int f = idx / (NR * 3);
            int r = (idx - f * NR * 3) / 3;
            int c = idx - f * NR * 3 - r * 3;
            sfeat[(c * NR + r) * NFPAD + f] = fg[idx];    // [c][r][f]
        }
        if (tid < HID) b1s[tid] = b1[j * HID + tid];
        if (tid < DIN) b2s[tid] = b2[j * DIN + tid];
    }
    __syncthreads();

    const int p0 = blockIdx.x * 256;                      // 256 pts per block

    // ================= Phase 1: 2 points per thread =================
    int   x0[2][3];
    float wq[2][3];
    #pragma unroll
    for (int q = 0; q < 2; ++q) {
        const float* ptp = pts + ((size_t)j * NP + p0 + q * 128 + tid) * 3;
        #pragma unroll
        for (int c = 0; c < 3; ++c) {
            float x = fminf(fmaxf(fmaf(ptp[c], 7.5f, 7.5f), 0.0f), 15.0f);
            int xi = (int)x;
            if (xi > NR - 2) xi = NR - 2;
            wq[q][c] = x - (float)xi;
            x0[q][c] = xi;
        }
    }

    ull hacc[2][16];
    {
        const float2* bv = (const float2*)b1s;
        #pragma unroll
        for (int i = 0; i < 16; ++i) {
            float2 bb = bv[i];
            ull p = pack2(bb.x, bb.y);
            hacc[0][i] = p; hacc[1][i] = p;
        }
    }

    #pragma unroll 1
    for (int c = 0; c < 3; ++c) {
        int   rb0 = (c * NR + x0[0][c]) * NFPAD;
        int   rb1 = (c * NR + x0[1][c]) * NFPAD;
        float wa = wq[0][c], wb = wq[1][c];

        #pragma unroll 1
        for (int fb = 0; fb < 10; ++fb) {                 // f = 4*fb .. 4*fb+3
            ull v2[2][4];
            {
                float4 g0 = *(const float4*)(sfeat + rb0 + fb * 4);
                float4 g1 = *(const float4*)(sfeat + rb0 + NFPAD + fb * 4);
                v2[0][0] = rep2(fmaf(wa, g1.x - g0.x, g0.x));
                v2[0][1] = rep2(fmaf(wa, g1.y - g0.y, g0.y));
                v2[0][2] = rep2(fmaf(wa, g1.z - g0.z, g0.z));
                v2[0][3] = rep2(fmaf(wa, g1.w - g0.w, g0.w));
            }
            {
                float4 g0 = *(const float4*)(sfeat + rb1 + fb * 4);
                float4 g1 = *(const float4*)(sfeat + rb1 + NFPAD + fb * 4);
                v2[1][0] = rep2(fmaf(wb, g1.x - g0.x, g0.x));
                v2[1][1] = rep2(fmaf(wb, g1.y - g0.y, g0.y));
                v2[1][2] = rep2(fmaf(wb, g1.z - g0.z, g0.z));
                v2[1][3] = rep2(fmaf(wb, g1.w - g0.w, g0.w));
            }
            #pragma unroll
            for (int ff = 0; ff < 4; ++ff) {
                int k = (fb * 4 + ff) * 3 + c;
                const ulonglong2* wr = (const ulonglong2*)(w1s + k * HID);
                #pragma unroll
                for (int i8 = 0; i8 < 8; ++i8) {
                    ulonglong2 wv = wr[i8];
                    hacc[0][2 * i8 + 0] = fma2(v2[0][ff], wv.x, hacc[0][2 * i8 + 0]);
                    hacc[0][2 * i8 + 1] = fma2(v2[0][ff], wv.y, hacc[0][2 * i8 + 1]);
                    hacc[1][2 * i8 + 0] = fma2(v2[1][ff], wv.x, hacc[1][2 * i8 + 0]);
                    hacc[1][2 * i8 + 1] = fma2(v2[1][ff], wv.y, hacc[1][2 * i8 + 1]);
                }
            }
        }
        // remainder f = 40, 41
        {
            float2 g0a = *(const float2*)(sfeat + rb0 + 40);
            float2 g1a = *(const float2*)(sfeat + rb0 + NFPAD + 40);
            float2 g0b = *(const float2*)(sfeat + rb1 + 40);
            float2 g1b = *(const float2*)(sfeat + rb1 + NFPAD + 40);
            ull vr[2][2];
            vr[0][0] = rep2(fmaf(wa, g1a.x - g0a.x, g0a.x));
            vr[0][1] = rep2(fmaf(wa, g1a.y - g0a.y, g0a.y));
            vr[1][0] = rep2(fmaf(wb, g1b.x - g0b.x, g0b.x));
            vr[1][1] = rep2(fmaf(wb, g1b.y - g0b.y, g0b.y));
            #pragma unroll
            for (int ff = 0; ff < 2; ++ff) {
                int k = (40 + ff) * 3 + c;
                const ulonglong2* wr = (const ulonglong2*)(w1s + k * HID);
                #pragma unroll
                for (int i8 = 0; i8 < 8; ++i8) {
                    ulonglong2 wv = wr[i8];
                    hacc[0][2 * i8 + 0] = fma2(vr[0][ff], wv.x, hacc[0][2 * i8 + 0]);
                    hacc[0][2 * i8 + 1] = fma2(vr[0][ff], wv.y, hacc[0][2 * i8 + 1]);
                    hacc[1][2 * i8 + 0] = fma2(vr[1][ff], wv.x, hacc[1][2 * i8 + 0]);
                    hacc[1][2 * i8 + 1] = fma2(vr[1][ff], wv.y, hacc[1][2 * i8 + 1]);
                }
            }
        }
    }

    // ================= Rounds: relu-store h -> phase 2 (per warp) =================
    float* hsw = hsall + warp * (HID * 36);               // [o][pt], stride 36

    #pragma unroll 1
    for (int q = 0; q < 2; ++q) {
        // ReLU + transpose to shared: hs[o][lane]
        #pragma unroll
        for (int i = 0; i < 16; ++i) {
            float h0, h1; unpack2(hacc[q][i], h0, h1);
            hsw[(2 * i + 0) * 36 + lane] = fmaxf(h0, 0.0f);
            hsw[(2 * i + 1) * 36 + lane] = fmaxf(h1, 0.0f);
        }
        __syncwarp();

        const int pw0 = p0 + q * 128 + warp * 32;         // warp's 32 points
        float*       outg = out + ((size_t)j * NP + pw0) * NOUTC;
        const float* indg = ind + ((size_t)j * NP + pw0) * NIND;

        // ind_feature copy (coalesced reads)
        for (int idx = lane; idx < 32 * NIND; idx += 32) {
            int pp = idx / NIND;
            int cc = idx - pp * NIND;
            outg[pp * NOUTC + cc] = indg[idx];
        }

        // Phase 2: 4 passes, lane = output channel k = i*32+lane
        #pragma unroll 1
        for (int i = 0; i < 4; ++i) {
            int  k     = i * 32 + lane;
            bool valid = (k < DIN);
            int  ks    = valid ? k : 0;

            ull wreg[HID];
            #pragma unroll
            for (int o = 0; o < HID; ++o) wreg[o] = rep2(w2t[o * DIN + ks]);
            ull binit = rep2(b2s[ks]);

            #pragma unroll 1
            for (int prq = 0; prq < 8; ++prq) {           // 4 points per iter
                ull acc01 = binit, acc23 = binit;
                #pragma unroll
                for (int o = 0; o < HID; ++o) {
                    ulonglong2 hh = *(const ulonglong2*)(hsw + o * 36 + prq * 4);
                    acc01 = fma2(hh.x, wreg[o], acc01);
                    acc23 = fma2(hh.y, wreg[o], acc23);
                }
                if (valid) {
                    float a0, a1, a2, a3;
                    unpack2(acc01, a0, a1);
                    unpack2(acc23, a2, a3);
                    int pb = prq * 4;
                    outg[(pb + 0) * NOUTC + NIND + k] = a0;
                    outg[(pb + 1) * NOUTC + NIND + k] = a1;
                    outg[(pb + 2) * NOUTC + NIND + k] = a2;
                    outg[(pb + 3) * NOUTC + NIND + k] = a3;
                }
            }
        }
        __syncwarp();   // hs reused next round
    }
}

extern "C" void kernel_launch(void* const* d_in, const int* in_sizes, int n_in,
                              void* d_out, int out_size)
{
    const float* pts     = (const float*)d_in[0];
    const float* feature = (const float*)d_in[1];
    const float* ind     = (const float*)d_in[2];
    const float* w1      = (const float*)d_in[3];
    const float* b1      = (const float*)d_in[4];
    const float* w2      = (const float*)d_in[5];
    const float* b2      = (const float*)d_in[6];
    float*       out     = (float*)d_out;

    const size_t smem = SMEM_FLOATS * sizeof(float);      // ~58.4 KB
    cudaFuncSetAttribute(v3d_fused_kernel,
                         cudaFuncAttributeMaxDynamicSharedMemorySize, (int)smem);

    dim3 grid(NP / 256, NJ);                              // (128, 24)
    dim3 block(128);
    v3d_fused_kernel<<<grid, block, smem>>>(pts, feature, ind, w1, b1, w2, b2, out);
}